// round 12
// baseline (speedup 1.0000x reference)
#include <cuda_runtime.h>
#include <cstdint>

#define SB   2048
#define DM   768
#define NH   12
#define DEP  64
#define NB   4
#define BHN  48

// ---- scratch (no cudaMalloc allowed) ----
__device__ float g_Qh[(size_t)BHN*SB*DEP];   // tf32-pre-rounded
__device__ float g_Kh[(size_t)BHN*SB*DEP];   // tf32-pre-rounded
__device__ float g_Vh[(size_t)BHN*SB*DEP];   // tf32-pre-rounded
__device__ float g_ctx[(size_t)NB*SB*DM];    // tf32-pre-rounded

// ======================= helpers =======================
__device__ __forceinline__ uint32_t f2tf(float x){
    uint32_t r; asm("cvt.rna.tf32.f32 %0, %1;" : "=r"(r) : "f"(x)); return r;
}
__device__ __forceinline__ float tfb(float x){
    return __uint_as_float(f2tf(x));
}
__device__ __forceinline__ void mma8(float* c, const uint32_t* a, const uint32_t* b){
    asm volatile("mma.sync.aligned.m16n8k8.row.col.f32.tf32.tf32.f32 "
        "{%0,%1,%2,%3}, {%4,%5,%6,%7}, {%8,%9}, {%0,%1,%2,%3};"
        : "+f"(c[0]), "+f"(c[1]), "+f"(c[2]), "+f"(c[3])
        : "r"(a[0]), "r"(a[1]), "r"(a[2]), "r"(a[3]), "r"(b[0]), "r"(b[1]));
}
__device__ __forceinline__ uint32_t smem_u32(const void* p){
    uint32_t a;
    asm("{ .reg .u64 t; cvta.to.shared.u64 t, %1; cvt.u32.u64 %0, t; }"
        : "=r"(a) : "l"(p));
    return a;
}
#define CPA16(dst, src) asm volatile("cp.async.cg.shared.global [%0], [%1], 16;" :: "r"(dst), "l"(src))
#define CPCOMMIT()      asm volatile("cp.async.commit_group;" ::: "memory")
#define CPWAIT(n)       asm volatile("cp.async.wait_group %0;" :: "n"(n) : "memory")

// ======================= fused QKV GEMM: Yz = Xz @ Wz^T =======================
// CTA 128x128, BK=32, cp.async double-buffered, 8 warps (2x4), warp 64x32. 2 CTAs/SM.
#define GST 36
#define G_SMEM (4*128*GST*4)   // 73728 B

__global__ __launch_bounds__(256,2)
void gemm_qkv(const float* __restrict__ x0, const float* __restrict__ x1,
              const float* __restrict__ x2,
              const float* __restrict__ w0, const float* __restrict__ w1,
              const float* __restrict__ w2,
              float* __restrict__ y0, float* __restrict__ y1,
              float* __restrict__ y2)
{
    extern __shared__ float sm[];
    float* As = sm;                 // [2][128][GST]
    float* Bs = sm + 2*128*GST;

    const int z = blockIdx.z;
    const float* X = z == 0 ? x0 : (z == 1 ? x1 : x2);
    const float* W = z == 0 ? w0 : (z == 1 ? w1 : w2);
    float*       Y = z == 0 ? y0 : (z == 1 ? y1 : y2);

    const int t = threadIdx.x, lane = t & 31, w = t >> 5;
    const int wm = w >> 2, wn = w & 3;
    const int r  = lane >> 2, cq = lane & 3;
    const int m0 = blockIdx.y << 7, n0 = blockIdx.x << 7;

    const uint32_t smbA = smem_u32(As), smbB = smem_u32(Bs);
    const int lrow = t >> 3, lc4 = (t & 7) << 2;

    float acc[4][4][4] = {};

    auto issue = [&](int kt, int buf){
        const uint32_t ab = smbA + buf * 128 * GST * 4;
        const uint32_t bb = smbB + buf * 128 * GST * 4;
#pragma unroll
        for (int i = 0; i < 4; i++){
            const int rr = lrow + i * 32;
            CPA16(ab + (rr * GST + lc4) * 4, X + (size_t)(m0 + rr) * DM + kt * 32 + lc4);
            CPA16(bb + (rr * GST + lc4) * 4, W + (size_t)(n0 + rr) * DM + kt * 32 + lc4);
        }
    };

    issue(0, 0); CPCOMMIT();
    issue(1, 1); CPCOMMIT();

    for (int kt = 0; kt < 24; kt++){
        const int b = kt & 1;
        if (kt < 23) CPWAIT(1); else CPWAIT(0);
        __syncthreads();

        const float* Ab = As + b * 128 * GST;
        const float* Bb = Bs + b * 128 * GST;
#pragma unroll
        for (int ks = 0; ks < 4; ks++){
            uint32_t af[4][4], bf[4][2];
#pragma unroll
            for (int mi = 0; mi < 4; mi++){
                const float* p = Ab + (wm * 64 + mi * 16 + r) * GST + ks * 8 + cq;
                af[mi][0] = f2tf(p[0]);
                af[mi][1] = f2tf(p[8 * GST]);
                af[mi][2] = f2tf(p[4]);
                af[mi][3] = f2tf(p[8 * GST + 4]);
            }
#pragma unroll
            for (int ni = 0; ni < 4; ni++){
                const float* p = Bb + (wn * 32 + ni * 8 + r) * GST + ks * 8 + cq;
                bf[ni][0] = f2tf(p[0]);
                bf[ni][1] = f2tf(p[4]);
            }
#pragma unroll
            for (int mi = 0; mi < 4; mi++)
#pragma unroll
                for (int ni = 0; ni < 4; ni++)
                    mma8(acc[mi][ni], af[mi], bf[ni]);
        }
        __syncthreads();
        if (kt + 2 < 24){ issue(kt + 2, b); CPCOMMIT(); }
    }

#pragma unroll
    for (int mi = 0; mi < 4; mi++)
#pragma unroll
    for (int ni = 0; ni < 4; ni++){
        const int col = n0 + wn * 32 + ni * 8 + cq * 2;
        const int h = col >> 6, d = col & 63;
#pragma unroll
        for (int rr = 0; rr < 2; rr++){
            const int grow = m0 + wm * 64 + mi * 16 + r + rr * 8;
            const int b_ = grow >> 11, s = grow & (SB - 1);
            float2 v = { tfb(acc[mi][ni][rr * 2 + 0]), tfb(acc[mi][ni][rr * 2 + 1]) };
            *(float2*)(Y + ((size_t)(b_ * NH + h) * SB + s) * DEP + d) = v;
        }
    }
}

// ======================= output GEMM: Y = ctx @ W^T + bias (ctx pre-rounded) ====
__global__ __launch_bounds__(256,2)
void gemm_out(const float* __restrict__ X, const float* __restrict__ W,
              float* __restrict__ Y, const float* __restrict__ bias)
{
    extern __shared__ float sm[];
    float* As = sm;
    float* Bs = sm + 2*128*GST;

    const int t = threadIdx.x, lane = t & 31, w = t >> 5;
    const int wm = w >> 2, wn = w & 3;
    const int r  = lane >> 2, cq = lane & 3;
    const int m0 = blockIdx.y << 7, n0 = blockIdx.x << 7;

    const uint32_t smbA = smem_u32(As), smbB = smem_u32(Bs);
    const int lrow = t >> 3, lc4 = (t & 7) << 2;

    float acc[4][4][4] = {};

    auto issue = [&](int kt, int buf){
        const uint32_t ab = smbA + buf * 128 * GST * 4;
        const uint32_t bb = smbB + buf * 128 * GST * 4;
#pragma unroll
        for (int i = 0; i < 4; i++){
            const int rr = lrow + i * 32;
            CPA16(ab + (rr * GST + lc4) * 4, X + (size_t)(m0 + rr) * DM + kt * 32 + lc4);
            CPA16(bb + (rr * GST + lc4) * 4, W + (size_t)(n0 + rr) * DM + kt * 32 + lc4);
        }
    };

    issue(0, 0); CPCOMMIT();
    issue(1, 1); CPCOMMIT();

    for (int kt = 0; kt < 24; kt++){
        const int b = kt & 1;
        if (kt < 23) CPWAIT(1); else CPWAIT(0);
        __syncthreads();

        const float* Ab = As + b * 128 * GST;
        const float* Bb = Bs + b * 128 * GST;
#pragma unroll
        for (int ks = 0; ks < 4; ks++){
            uint32_t af[4][4], bf[4][2];
#pragma unroll
            for (int mi = 0; mi < 4; mi++){
                const float* p = Ab + (wm * 64 + mi * 16 + r) * GST + ks * 8 + cq;
                af[mi][0] = __float_as_uint(p[0]);         // ctx pre-rounded
                af[mi][1] = __float_as_uint(p[8 * GST]);
                af[mi][2] = __float_as_uint(p[4]);
                af[mi][3] = __float_as_uint(p[8 * GST + 4]);
            }
#pragma unroll
            for (int ni = 0; ni < 4; ni++){
                const float* p = Bb + (wn * 32 + ni * 8 + r) * GST + ks * 8 + cq;
                bf[ni][0] = f2tf(p[0]);
                bf[ni][1] = f2tf(p[4]);
            }
#pragma unroll
            for (int mi = 0; mi < 4; mi++)
#pragma unroll
                for (int ni = 0; ni < 4; ni++)
                    mma8(acc[mi][ni], af[mi], bf[ni]);
        }
        __syncthreads();
        if (kt + 2 < 24){ issue(kt + 2, b); CPCOMMIT(); }
    }

#pragma unroll
    for (int mi = 0; mi < 4; mi++)
#pragma unroll
    for (int ni = 0; ni < 4; ni++){
        const int col = n0 + wn * 32 + ni * 8 + cq * 2;
        float2 bb = *(const float2*)(bias + col);
#pragma unroll
        for (int rr = 0; rr < 2; rr++){
            const int grow = m0 + wm * 64 + mi * 16 + r + rr * 8;
            float2 v = { acc[mi][ni][rr * 2 + 0] + bb.x, acc[mi][ni][rr * 2 + 1] + bb.y };
            *(float2*)(Y + (size_t)grow * DM + col) = v;
        }
    }
}

// ======================= flash attention (mma.sync tf32) =======================
// CTA: 128 q-rows, 4 warps (M=32/warp), key tiles of 64, cp.async 2-stage.
// Q/K/V pre-rounded tf32 bits. No max-subtraction; O accumulates in regs.
// Head-0 CTAs normalize their own attn rows in the epilogue (no attn_scale kernel).
#define FST 68
#define F_TILE (64*FST)
#define F_SMEM ((4*F_TILE + 128*FST)*4)   // 104448 B -> 2 CTAs/SM

__global__ __launch_bounds__(128,2)
void flash_tc(const float* __restrict__ Qh, const float* __restrict__ Kh,
              const float* __restrict__ Vh, float* __restrict__ ctx,
              float* __restrict__ attn)
{
    extern __shared__ float sm[];
    float* Ks = sm;                     // [2][64][FST]
    float* Vs = sm + 2 * F_TILE;        // [2][64][FST]
    float* Ps = sm + 4 * F_TILE;        // [128][FST]

    const int t = threadIdx.x, lane = t & 31, w = t >> 5;
    const int r = lane >> 2, cq = lane & 3;
    const int q0 = blockIdx.x << 7;
    const int bh = blockIdx.y;
    const int bi = bh / NH, h = bh % NH;
    const bool head0 = (h == 0);
    const float* Qb = Qh + (size_t)bh * SB * DEP;
    const float* Kb = Kh + (size_t)bh * SB * DEP;
    const float* Vb = Vh + (size_t)bh * SB * DEP;

    const uint32_t smbK = smem_u32(Ks), smbV = smem_u32(Vs);

    // Q fragments persistent (already tf32 bits)
    uint32_t aq[2][8][4];
#pragma unroll
    for (int mi = 0; mi < 2; mi++){
        const float* Q0 = Qb + (size_t)(q0 + w * 32 + mi * 16 + r) * DEP;
        const float* Q8 = Q0 + 8 * DEP;
#pragma unroll
        for (int ks = 0; ks < 8; ks++){
            aq[mi][ks][0] = __float_as_uint(Q0[ks * 8 + cq]);
            aq[mi][ks][1] = __float_as_uint(Q8[ks * 8 + cq]);
            aq[mi][ks][2] = __float_as_uint(Q0[ks * 8 + cq + 4]);
            aq[mi][ks][3] = __float_as_uint(Q8[ks * 8 + cq + 4]);
        }
    }

    auto issue = [&](int kt, int buf){
        const int k0 = kt << 6;
#pragma unroll
        for (int i = 0; i < 8; i++){
            int idx = t + i * 128;
            int row = idx >> 4, c4 = (idx & 15) << 2;
            CPA16(smbK + (buf * F_TILE + row * FST + c4) * 4,
                  Kb + (size_t)(k0 + row) * DEP + c4);
            CPA16(smbV + (buf * F_TILE + row * FST + c4) * 4,
                  Vb + (size_t)(k0 + row) * DEP + c4);
        }
    };

    issue(0, 0); CPCOMMIT();
    issue(1, 1); CPCOMMIT();

    float oacc[2][8][4] = {};
    float lr[4] = {0.f, 0.f, 0.f, 0.f};

    for (int kt = 0; kt < 32; kt++){
        const int b = kt & 1;
        if (kt < 31) CPWAIT(1); else CPWAIT(0);
        __syncthreads();

        // ---- S = Q K^T ----
        float sacc[2][8][4] = {};
        const float* Kt = Ks + b * F_TILE;
#pragma unroll
        for (int ks = 0; ks < 8; ks++){
#pragma unroll
            for (int ni = 0; ni < 8; ni++){
                uint32_t bf[2];
                const float* p = Kt + (ni * 8 + r) * FST + ks * 8 + cq;
                bf[0] = __float_as_uint(p[0]);
                bf[1] = __float_as_uint(p[4]);
                mma8(sacc[0][ni], aq[0][ks], bf);
                mma8(sacc[1][ni], aq[1][ks], bf);
            }
        }

        // ---- exp, row sums, P -> smem (+ head-0 attn, unnormalized) ----
#pragma unroll
        for (int mi = 0; mi < 2; mi++){
            float* Pr = Ps + (w * 32 + mi * 16 + r) * FST;
            float* ap0 = head0 ? attn + ((size_t)bi * SB + q0 + w * 32 + mi * 16 + r) * SB
                                 + (kt << 6)
                               : nullptr;
#pragma unroll
            for (int ni = 0; ni < 8; ni++){
                float e0 = __expf(sacc[mi][ni][0] * 0.125f);
                float e1 = __expf(sacc[mi][ni][1] * 0.125f);
                float e2 = __expf(sacc[mi][ni][2] * 0.125f);
                float e3 = __expf(sacc[mi][ni][3] * 0.125f);
                lr[mi * 2 + 0] += e0 + e1;
                lr[mi * 2 + 1] += e2 + e3;
                const int c = ni * 8 + cq * 2;
                *(float2*)(Pr + c)           = make_float2(tfb(e0), tfb(e1));
                *(float2*)(Pr + 8 * FST + c) = make_float2(tfb(e2), tfb(e3));
                if (head0){
                    *(float2*)(ap0 + c)                  = make_float2(e0, e1);
                    *(float2*)(ap0 + (size_t)8 * SB + c) = make_float2(e2, e3);
                }
            }
        }
        __syncwarp();

        // ---- O += P V ----
        const float* Vt = Vs + b * F_TILE;
#pragma unroll
        for (int ks = 0; ks < 8; ks++){
            uint32_t apf[2][4];
#pragma unroll
            for (int mi = 0; mi < 2; mi++){
                const float* pq = Ps + (w * 32 + mi * 16 + r) * FST + ks * 8 + cq;
                apf[mi][0] = __float_as_uint(pq[0]);
                apf[mi][1] = __float_as_uint(pq[8 * FST]);
                apf[mi][2] = __float_as_uint(pq[4]);
                apf[mi][3] = __float_as_uint(pq[8 * FST + 4]);
            }
#pragma unroll
            for (int ni = 0; ni < 8; ni++){
                uint32_t bf[2];
                const float* p = Vt + (ks * 8 + cq) * FST + ni * 8 + r;
                bf[0] = __float_as_uint(p[0]);
                bf[1] = __float_as_uint(p[4 * FST]);
                mma8(oacc[0][ni], apf[0], bf);
                mma8(oacc[1][ni], apf[1], bf);
            }
        }

        __syncthreads();
        if (kt + 2 < 32){ issue(kt + 2, b); CPCOMMIT(); }
    }

    // ---- epilogue: ctx (pre-rounded) + in-place attn normalization (head0) ----
#pragma unroll
    for (int i = 0; i < 4; i++){
        lr[i] += __shfl_xor_sync(0xffffffffu, lr[i], 1);
        lr[i] += __shfl_xor_sync(0xffffffffu, lr[i], 2);
    }
#pragma unroll
    for (int mi = 0; mi < 2; mi++){
        const int s0 = q0 + w * 32 + mi * 16 + r;
        const float inv0 = 1.f / lr[mi * 2], inv1 = 1.f / lr[mi * 2 + 1];
        float* c0p = ctx + ((size_t)bi * SB + s0) * DM + h * DEP;
        float* c1p = c0p + (size_t)8 * DM;
#pragma unroll
        for (int ni = 0; ni < 8; ni++){
            const int c = ni * 8 + cq * 2;
            *(float2*)(c0p + c) = make_float2(tfb(oacc[mi][ni][0] * inv0),
                                              tfb(oacc[mi][ni][1] * inv0));
            *(float2*)(c1p + c) = make_float2(tfb(oacc[mi][ni][2] * inv1),
                                              tfb(oacc[mi][ni][3] * inv1));
        }
    }

    if (head0){
        // stash 1/l for the CTA's 128 rows in (now dead) K-smem
        float* sinv = Ks;
        if (cq == 0){
#pragma unroll
            for (int mi = 0; mi < 2; mi++){
                sinv[w * 32 + mi * 16 + r]     = 1.f / lr[mi * 2];
                sinv[w * 32 + mi * 16 + r + 8] = 1.f / lr[mi * 2 + 1];
            }
        }
        __syncthreads();   // sinv visible + this CTA's attn writes ordered
        // rescale own 128 rows x 2048 cols in place (float4 granularity)
        for (int i = t; i < 128 * (SB / 4); i += 128){
            const int row = i >> 9;            // SB/4 = 512 float4 per row
            const int c4  = i & 511;
            const float inv = sinv[row];
            float4* p = (float4*)(attn + ((size_t)bi * SB + q0 + row) * SB) + c4;
            float4 v = *p;
            v.x *= inv; v.y *= inv; v.z *= inv; v.w *= inv;
            *p = v;
        }
    }
}

// ======================= launch =======================
extern "C" void kernel_launch(void* const* d_in, const int* in_sizes, int n_in,
                              void* d_out, int out_size)
{
    const float* q  = (const float*)d_in[0];
    const float* k  = (const float*)d_in[1];
    const float* v  = (const float*)d_in[2];
    const float* wq = (const float*)d_in[3];
    const float* wk = (const float*)d_in[4];
    const float* wv = (const float*)d_in[5];
    const float* wd = (const float*)d_in[6];
    const float* bd = (const float*)d_in[7];
    float* out = (float*)d_out;

    float *Qh, *Kh, *Vh, *ctx;
    cudaGetSymbolAddress((void**)&Qh,  g_Qh);
    cudaGetSymbolAddress((void**)&Kh,  g_Kh);
    cudaGetSymbolAddress((void**)&Vh,  g_Vh);
    cudaGetSymbolAddress((void**)&ctx, g_ctx);

    cudaFuncSetAttribute(gemm_qkv, cudaFuncAttributeMaxDynamicSharedMemorySize, G_SMEM);
    cudaFuncSetAttribute(gemm_out, cudaFuncAttributeMaxDynamicSharedMemorySize, G_SMEM);
    cudaFuncSetAttribute(flash_tc, cudaFuncAttributeMaxDynamicSharedMemorySize, F_SMEM);

    dim3 gq(DM / 128, (NB * SB) / 128, 3);    // 6 x 64 x 3 (Q,K,V fused)
    gemm_qkv<<<gq, 256, G_SMEM>>>(q, k, v, wq, wk, wv, Qh, Kh, Vh);

    const size_t OUTOFF = (size_t)NB * SB * DM;
    flash_tc<<<dim3(SB / 128, BHN), 128, F_SMEM>>>(Qh, Kh, Vh, ctx, out + OUTOFF);

    dim3 gg(DM / 128, (NB * SB) / 128);       // 6 x 64
    gemm_out<<<gg, 256, G_SMEM>>>(ctx, wd, out, bd);
}

// round 13
// speedup vs baseline: 1.0726x; 1.0726x over previous
#include <cuda_runtime.h>
#include <cstdint>

#define SB   2048
#define DM   768
#define NH   12
#define DEP  64
#define NB   4
#define BHN  48

// ---- scratch (no cudaMalloc allowed) ----
__device__ float g_Qh[(size_t)BHN*SB*DEP];   // tf32-pre-rounded
__device__ float g_Kh[(size_t)BHN*SB*DEP];   // tf32-pre-rounded
__device__ float g_Vh[(size_t)BHN*SB*DEP];   // tf32-pre-rounded
__device__ float g_ctx[(size_t)NB*SB*DM];    // tf32-pre-rounded
__device__ float g_L[(size_t)NB*SB];         // head-0 row sums [b, q]

// ======================= helpers =======================
__device__ __forceinline__ uint32_t f2tf(float x){
    uint32_t r; asm("cvt.rna.tf32.f32 %0, %1;" : "=r"(r) : "f"(x)); return r;
}
__device__ __forceinline__ float tfb(float x){
    return __uint_as_float(f2tf(x));
}
__device__ __forceinline__ void mma8(float* c, const uint32_t* a, const uint32_t* b){
    asm volatile("mma.sync.aligned.m16n8k8.row.col.f32.tf32.tf32.f32 "
        "{%0,%1,%2,%3}, {%4,%5,%6,%7}, {%8,%9}, {%0,%1,%2,%3};"
        : "+f"(c[0]), "+f"(c[1]), "+f"(c[2]), "+f"(c[3])
        : "r"(a[0]), "r"(a[1]), "r"(a[2]), "r"(a[3]), "r"(b[0]), "r"(b[1]));
}
__device__ __forceinline__ uint32_t smem_u32(const void* p){
    uint32_t a;
    asm("{ .reg .u64 t; cvta.to.shared.u64 t, %1; cvt.u32.u64 %0, t; }"
        : "=r"(a) : "l"(p));
    return a;
}
#define CPA16(dst, src) asm volatile("cp.async.cg.shared.global [%0], [%1], 16;" :: "r"(dst), "l"(src))
#define CPCOMMIT()      asm volatile("cp.async.commit_group;" ::: "memory")
#define CPWAIT(n)       asm volatile("cp.async.wait_group %0;" :: "n"(n) : "memory")

// ======================= fused QKV GEMM: Yz = Xz @ Wz^T =======================
// CTA 128x128, BK=32, cp.async double-buffered, 8 warps (2x4), warp 64x32. 2 CTAs/SM.
#define GST 36
#define G_SMEM (4*128*GST*4)   // 73728 B

__global__ __launch_bounds__(256,2)
void gemm_qkv(const float* __restrict__ x0, const float* __restrict__ x1,
              const float* __restrict__ x2,
              const float* __restrict__ w0, const float* __restrict__ w1,
              const float* __restrict__ w2,
              float* __restrict__ y0, float* __restrict__ y1,
              float* __restrict__ y2)
{
    extern __shared__ float sm[];
    float* As = sm;                 // [2][128][GST]
    float* Bs = sm + 2*128*GST;

    const int z = blockIdx.z;
    const float* X = z == 0 ? x0 : (z == 1 ? x1 : x2);
    const float* W = z == 0 ? w0 : (z == 1 ? w1 : w2);
    float*       Y = z == 0 ? y0 : (z == 1 ? y1 : y2);

    const int t = threadIdx.x, lane = t & 31, w = t >> 5;
    const int wm = w >> 2, wn = w & 3;
    const int r  = lane >> 2, cq = lane & 3;
    const int m0 = blockIdx.y << 7, n0 = blockIdx.x << 7;

    const uint32_t smbA = smem_u32(As), smbB = smem_u32(Bs);
    const int lrow = t >> 3, lc4 = (t & 7) << 2;

    float acc[4][4][4] = {};

    auto issue = [&](int kt, int buf){
        const uint32_t ab = smbA + buf * 128 * GST * 4;
        const uint32_t bb = smbB + buf * 128 * GST * 4;
#pragma unroll
        for (int i = 0; i < 4; i++){
            const int rr = lrow + i * 32;
            CPA16(ab + (rr * GST + lc4) * 4, X + (size_t)(m0 + rr) * DM + kt * 32 + lc4);
            CPA16(bb + (rr * GST + lc4) * 4, W + (size_t)(n0 + rr) * DM + kt * 32 + lc4);
        }
    };

    issue(0, 0); CPCOMMIT();
    issue(1, 1); CPCOMMIT();

    for (int kt = 0; kt < 24; kt++){
        const int b = kt & 1;
        if (kt < 23) CPWAIT(1); else CPWAIT(0);
        __syncthreads();

        const float* Ab = As + b * 128 * GST;
        const float* Bb = Bs + b * 128 * GST;
#pragma unroll
        for (int ks = 0; ks < 4; ks++){
            uint32_t af[4][4], bf[4][2];
#pragma unroll
            for (int mi = 0; mi < 4; mi++){
                const float* p = Ab + (wm * 64 + mi * 16 + r) * GST + ks * 8 + cq;
                af[mi][0] = f2tf(p[0]);
                af[mi][1] = f2tf(p[8 * GST]);
                af[mi][2] = f2tf(p[4]);
                af[mi][3] = f2tf(p[8 * GST + 4]);
            }
#pragma unroll
            for (int ni = 0; ni < 4; ni++){
                const float* p = Bb + (wn * 32 + ni * 8 + r) * GST + ks * 8 + cq;
                bf[ni][0] = f2tf(p[0]);
                bf[ni][1] = f2tf(p[4]);
            }
#pragma unroll
            for (int mi = 0; mi < 4; mi++)
#pragma unroll
                for (int ni = 0; ni < 4; ni++)
                    mma8(acc[mi][ni], af[mi], bf[ni]);
        }
        __syncthreads();
        if (kt + 2 < 24){ issue(kt + 2, b); CPCOMMIT(); }
    }

#pragma unroll
    for (int mi = 0; mi < 4; mi++)
#pragma unroll
    for (int ni = 0; ni < 4; ni++){
        const int col = n0 + wn * 32 + ni * 8 + cq * 2;
        const int h = col >> 6, d = col & 63;
#pragma unroll
        for (int rr = 0; rr < 2; rr++){
            const int grow = m0 + wm * 64 + mi * 16 + r + rr * 8;
            const int b_ = grow >> 11, s = grow & (SB - 1);
            float2 v = { tfb(acc[mi][ni][rr * 2 + 0]), tfb(acc[mi][ni][rr * 2 + 1]) };
            *(float2*)(Y + ((size_t)(b_ * NH + h) * SB + s) * DEP + d) = v;
        }
    }
}

// ======================= output GEMM + attn scaling =======================
// z=0: Y = ctx @ W^T + bias (ctx pre-rounded). z=1: attn row rescale by 1/Lrow.
__global__ __launch_bounds__(256,2)
void gemm_out(const float* __restrict__ X, const float* __restrict__ W,
              float* __restrict__ Y, const float* __restrict__ bias,
              float* __restrict__ attn, const float* __restrict__ Lrow)
{
    extern __shared__ float sm[];

    if (blockIdx.z == 1){
        // ---- attn normalization slice: 384 CTAs over 8192 rows ----
        const int id = blockIdx.y * gridDim.x + blockIdx.x;   // 0..383
        const int nc = gridDim.x * gridDim.y;                 // 384
        for (int rowg = id; rowg < NB * SB; rowg += nc){
            const float inv = 1.f / Lrow[rowg];
            float4* p = (float4*)(attn + (size_t)rowg * SB);
            for (int i = threadIdx.x; i < SB / 4; i += 256){
                float4 v = p[i];
                v.x *= inv; v.y *= inv; v.z *= inv; v.w *= inv;
                p[i] = v;
            }
        }
        return;
    }

    float* As = sm;
    float* Bs = sm + 2*128*GST;

    const int t = threadIdx.x, lane = t & 31, w = t >> 5;
    const int wm = w >> 2, wn = w & 3;
    const int r  = lane >> 2, cq = lane & 3;
    const int m0 = blockIdx.y << 7, n0 = blockIdx.x << 7;

    const uint32_t smbA = smem_u32(As), smbB = smem_u32(Bs);
    const int lrow = t >> 3, lc4 = (t & 7) << 2;

    float acc[4][4][4] = {};

    auto issue = [&](int kt, int buf){
        const uint32_t ab = smbA + buf * 128 * GST * 4;
        const uint32_t bb = smbB + buf * 128 * GST * 4;
#pragma unroll
        for (int i = 0; i < 4; i++){
            const int rr = lrow + i * 32;
            CPA16(ab + (rr * GST + lc4) * 4, X + (size_t)(m0 + rr) * DM + kt * 32 + lc4);
            CPA16(bb + (rr * GST + lc4) * 4, W + (size_t)(n0 + rr) * DM + kt * 32 + lc4);
        }
    };

    issue(0, 0); CPCOMMIT();
    issue(1, 1); CPCOMMIT();

    for (int kt = 0; kt < 24; kt++){
        const int b = kt & 1;
        if (kt < 23) CPWAIT(1); else CPWAIT(0);
        __syncthreads();

        const float* Ab = As + b * 128 * GST;
        const float* Bb = Bs + b * 128 * GST;
#pragma unroll
        for (int ks = 0; ks < 4; ks++){
            uint32_t af[4][4], bf[4][2];
#pragma unroll
            for (int mi = 0; mi < 4; mi++){
                const float* p = Ab + (wm * 64 + mi * 16 + r) * GST + ks * 8 + cq;
                af[mi][0] = __float_as_uint(p[0]);         // ctx pre-rounded
                af[mi][1] = __float_as_uint(p[8 * GST]);
                af[mi][2] = __float_as_uint(p[4]);
                af[mi][3] = __float_as_uint(p[8 * GST + 4]);
            }
#pragma unroll
            for (int ni = 0; ni < 4; ni++){
                const float* p = Bb + (wn * 32 + ni * 8 + r) * GST + ks * 8 + cq;
                bf[ni][0] = f2tf(p[0]);
                bf[ni][1] = f2tf(p[4]);
            }
#pragma unroll
            for (int mi = 0; mi < 4; mi++)
#pragma unroll
                for (int ni = 0; ni < 4; ni++)
                    mma8(acc[mi][ni], af[mi], bf[ni]);
        }
        __syncthreads();
        if (kt + 2 < 24){ issue(kt + 2, b); CPCOMMIT(); }
    }

#pragma unroll
    for (int mi = 0; mi < 4; mi++)
#pragma unroll
    for (int ni = 0; ni < 4; ni++){
        const int col = n0 + wn * 32 + ni * 8 + cq * 2;
        float2 bb = *(const float2*)(bias + col);
#pragma unroll
        for (int rr = 0; rr < 2; rr++){
            const int grow = m0 + wm * 64 + mi * 16 + r + rr * 8;
            float2 v = { acc[mi][ni][rr * 2 + 0] + bb.x, acc[mi][ni][rr * 2 + 1] + bb.y };
            *(float2*)(Y + (size_t)grow * DM + col) = v;
        }
    }
}

// ======================= flash attention (mma.sync tf32) =======================
// CTA: 128 q-rows, 4 warps (M=32/warp), key tiles of 64, cp.async 2-stage.
// Q/K/V pre-rounded tf32 bits. No max-subtraction; O accumulates in regs.
#define FST 68
#define F_TILE (64*FST)
#define F_SMEM ((4*F_TILE + 128*FST)*4)   // 104448 B -> 2 CTAs/SM

__global__ __launch_bounds__(128,2)
void flash_tc(const float* __restrict__ Qh, const float* __restrict__ Kh,
              const float* __restrict__ Vh, float* __restrict__ ctx,
              float* __restrict__ Lrow, float* __restrict__ attn)
{
    extern __shared__ float sm[];
    float* Ks = sm;                     // [2][64][FST]
    float* Vs = sm + 2 * F_TILE;        // [2][64][FST]
    float* Ps = sm + 4 * F_TILE;        // [128][FST]

    const int t = threadIdx.x, lane = t & 31, w = t >> 5;
    const int r = lane >> 2, cq = lane & 3;
    const int q0 = blockIdx.x << 7;
    const int bh = blockIdx.y;
    const int bi = bh / NH, h = bh % NH;
    const bool head0 = (h == 0);
    const float* Qb = Qh + (size_t)bh * SB * DEP;
    const float* Kb = Kh + (size_t)bh * SB * DEP;
    const float* Vb = Vh + (size_t)bh * SB * DEP;

    const uint32_t smbK = smem_u32(Ks), smbV = smem_u32(Vs);

    // Q fragments persistent (already tf32 bits)
    uint32_t aq[2][8][4];
#pragma unroll
    for (int mi = 0; mi < 2; mi++){
        const float* Q0 = Qb + (size_t)(q0 + w * 32 + mi * 16 + r) * DEP;
        const float* Q8 = Q0 + 8 * DEP;
#pragma unroll
        for (int ks = 0; ks < 8; ks++){
            aq[mi][ks][0] = __float_as_uint(Q0[ks * 8 + cq]);
            aq[mi][ks][1] = __float_as_uint(Q8[ks * 8 + cq]);
            aq[mi][ks][2] = __float_as_uint(Q0[ks * 8 + cq + 4]);
            aq[mi][ks][3] = __float_as_uint(Q8[ks * 8 + cq + 4]);
        }
    }

    auto issue = [&](int kt, int buf){
        const int k0 = kt << 6;
#pragma unroll
        for (int i = 0; i < 8; i++){
            int idx = t + i * 128;
            int row = idx >> 4, c4 = (idx & 15) << 2;
            CPA16(smbK + (buf * F_TILE + row * FST + c4) * 4,
                  Kb + (size_t)(k0 + row) * DEP + c4);
            CPA16(smbV + (buf * F_TILE + row * FST + c4) * 4,
                  Vb + (size_t)(k0 + row) * DEP + c4);
        }
    };

    issue(0, 0); CPCOMMIT();
    issue(1, 1); CPCOMMIT();

    float oacc[2][8][4] = {};
    float lr[4] = {0.f, 0.f, 0.f, 0.f};

    for (int kt = 0; kt < 32; kt++){
        const int b = kt & 1;
        if (kt < 31) CPWAIT(1); else CPWAIT(0);
        __syncthreads();

        // ---- S = Q K^T ----
        float sacc[2][8][4] = {};
        const float* Kt = Ks + b * F_TILE;
#pragma unroll
        for (int ks = 0; ks < 8; ks++){
#pragma unroll
            for (int ni = 0; ni < 8; ni++){
                uint32_t bf[2];
                const float* p = Kt + (ni * 8 + r) * FST + ks * 8 + cq;
                bf[0] = __float_as_uint(p[0]);
                bf[1] = __float_as_uint(p[4]);
                mma8(sacc[0][ni], aq[0][ks], bf);
                mma8(sacc[1][ni], aq[1][ks], bf);
            }
        }

        // ---- exp, row sums, P -> smem (+ head-0 attn, unnormalized) ----
#pragma unroll
        for (int mi = 0; mi < 2; mi++){
            float* Pr = Ps + (w * 32 + mi * 16 + r) * FST;
            float* ap0 = head0 ? attn + ((size_t)bi * SB + q0 + w * 32 + mi * 16 + r) * SB
                                 + (kt << 6)
                               : nullptr;
#pragma unroll
            for (int ni = 0; ni < 8; ni++){
                float e0 = __expf(sacc[mi][ni][0] * 0.125f);
                float e1 = __expf(sacc[mi][ni][1] * 0.125f);
                float e2 = __expf(sacc[mi][ni][2] * 0.125f);
                float e3 = __expf(sacc[mi][ni][3] * 0.125f);
                lr[mi * 2 + 0] += e0 + e1;
                lr[mi * 2 + 1] += e2 + e3;
                const int c = ni * 8 + cq * 2;
                *(float2*)(Pr + c)           = make_float2(tfb(e0), tfb(e1));
                *(float2*)(Pr + 8 * FST + c) = make_float2(tfb(e2), tfb(e3));
                if (head0){
                    *(float2*)(ap0 + c)                  = make_float2(e0, e1);
                    *(float2*)(ap0 + (size_t)8 * SB + c) = make_float2(e2, e3);
                }
            }
        }
        __syncwarp();

        // ---- O += P V ----
        const float* Vt = Vs + b * F_TILE;
#pragma unroll
        for (int ks = 0; ks < 8; ks++){
            uint32_t apf[2][4];
#pragma unroll
            for (int mi = 0; mi < 2; mi++){
                const float* pq = Ps + (w * 32 + mi * 16 + r) * FST + ks * 8 + cq;
                apf[mi][0] = __float_as_uint(pq[0]);
                apf[mi][1] = __float_as_uint(pq[8 * FST]);
                apf[mi][2] = __float_as_uint(pq[4]);
                apf[mi][3] = __float_as_uint(pq[8 * FST + 4]);
            }
#pragma unroll
            for (int ni = 0; ni < 8; ni++){
                uint32_t bf[2];
                const float* p = Vt + (ks * 8 + cq) * FST + ni * 8 + r;
                bf[0] = __float_as_uint(p[0]);
                bf[1] = __float_as_uint(p[4 * FST]);
                mma8(oacc[0][ni], apf[0], bf);
                mma8(oacc[1][ni], apf[1], bf);
            }
        }

        __syncthreads();
        if (kt + 2 < 32){ issue(kt + 2, b); CPCOMMIT(); }
    }

    // ---- epilogue (store ctx pre-rounded for the final GEMM) ----
#pragma unroll
    for (int i = 0; i < 4; i++){
        lr[i] += __shfl_xor_sync(0xffffffffu, lr[i], 1);
        lr[i] += __shfl_xor_sync(0xffffffffu, lr[i], 2);
    }
#pragma unroll
    for (int mi = 0; mi < 2; mi++){
        const int s0 = q0 + w * 32 + mi * 16 + r;
        const float inv0 = 1.f / lr[mi * 2], inv1 = 1.f / lr[mi * 2 + 1];
        float* c0p = ctx + ((size_t)bi * SB + s0) * DM + h * DEP;
        float* c1p = c0p + (size_t)8 * DM;
#pragma unroll
        for (int ni = 0; ni < 8; ni++){
            const int c = ni * 8 + cq * 2;
            *(float2*)(c0p + c) = make_float2(tfb(oacc[mi][ni][0] * inv0),
                                              tfb(oacc[mi][ni][1] * inv0));
            *(float2*)(c1p + c) = make_float2(tfb(oacc[mi][ni][2] * inv1),
                                              tfb(oacc[mi][ni][3] * inv1));
        }
        if (head0 && cq == 0){
            Lrow[(size_t)bi * SB + s0]     = lr[mi * 2];
            Lrow[(size_t)bi * SB + s0 + 8] = lr[mi * 2 + 1];
        }
    }
}

// ======================= launch =======================
extern "C" void kernel_launch(void* const* d_in, const int* in_sizes, int n_in,
                              void* d_out, int out_size)
{
    const float* q  = (const float*)d_in[0];
    const float* k  = (const float*)d_in[1];
    const float* v  = (const float*)d_in[2];
    const float* wq = (const float*)d_in[3];
    const float* wk = (const float*)d_in[4];
    const float* wv = (const float*)d_in[5];
    const float* wd = (const float*)d_in[6];
    const float* bd = (const float*)d_in[7];
    float* out = (float*)d_out;

    float *Qh, *Kh, *Vh, *ctx, *Lr;
    cudaGetSymbolAddress((void**)&Qh,  g_Qh);
    cudaGetSymbolAddress((void**)&Kh,  g_Kh);
    cudaGetSymbolAddress((void**)&Vh,  g_Vh);
    cudaGetSymbolAddress((void**)&ctx, g_ctx);
    cudaGetSymbolAddress((void**)&Lr,  g_L);

    cudaFuncSetAttribute(gemm_qkv, cudaFuncAttributeMaxDynamicSharedMemorySize, G_SMEM);
    cudaFuncSetAttribute(gemm_out, cudaFuncAttributeMaxDynamicSharedMemorySize, G_SMEM);
    cudaFuncSetAttribute(flash_tc, cudaFuncAttributeMaxDynamicSharedMemorySize, F_SMEM);

    dim3 gq(DM / 128, (NB * SB) / 128, 3);    // 6 x 64 x 3 (Q,K,V fused)
    gemm_qkv<<<gq, 256, G_SMEM>>>(q, k, v, wq, wk, wv, Qh, Kh, Vh);

    const size_t OUTOFF = (size_t)NB * SB * DM;
    flash_tc<<<dim3(SB / 128, BHN), 128, F_SMEM>>>(Qh, Kh, Vh, ctx, Lr, out + OUTOFF);

    dim3 gg(DM / 128, (NB * SB) / 128, 2);    // 6 x 64 x 2 (gemm + attn scale)
    gemm_out<<<gg, 256, G_SMEM>>>(ctx, wd, out, bd, out + OUTOFF, Lr);
}

// round 14
// speedup vs baseline: 1.0942x; 1.0201x over previous
#include <cuda_runtime.h>
#include <cstdint>

#define SB   2048
#define DM   768
#define NH   12
#define DEP  64
#define NB   4
#define BHN  48

// ---- scratch (no cudaMalloc allowed) ----
__device__ float g_Qh[(size_t)BHN*SB*DEP];   // tf32-pre-rounded
__device__ float g_Kh[(size_t)BHN*SB*DEP];   // tf32-pre-rounded
__device__ float g_Vh[(size_t)BHN*SB*DEP];   // tf32-pre-rounded
__device__ float g_ctx[(size_t)NB*SB*DM];    // tf32-pre-rounded
__device__ float g_L[(size_t)NB*SB];         // head-0 row sums [b, q]

// ======================= helpers =======================
__device__ __forceinline__ uint32_t f2tf(float x){
    uint32_t r; asm("cvt.rna.tf32.f32 %0, %1;" : "=r"(r) : "f"(x)); return r;
}
__device__ __forceinline__ float tfb(float x){
    return __uint_as_float(f2tf(x));
}
__device__ __forceinline__ void mma8(float* c, const uint32_t* a, const uint32_t* b){
    asm volatile("mma.sync.aligned.m16n8k8.row.col.f32.tf32.tf32.f32 "
        "{%0,%1,%2,%3}, {%4,%5,%6,%7}, {%8,%9}, {%0,%1,%2,%3};"
        : "+f"(c[0]), "+f"(c[1]), "+f"(c[2]), "+f"(c[3])
        : "r"(a[0]), "r"(a[1]), "r"(a[2]), "r"(a[3]), "r"(b[0]), "r"(b[1]));
}
__device__ __forceinline__ uint32_t smem_u32(const void* p){
    uint32_t a;
    asm("{ .reg .u64 t; cvta.to.shared.u64 t, %1; cvt.u32.u64 %0, t; }"
        : "=r"(a) : "l"(p));
    return a;
}
#define CPA16(dst, src) asm volatile("cp.async.cg.shared.global [%0], [%1], 16;" :: "r"(dst), "l"(src))
#define CPCOMMIT()      asm volatile("cp.async.commit_group;" ::: "memory")
#define CPWAIT(n)       asm volatile("cp.async.wait_group %0;" :: "n"(n) : "memory")

// ======================= fused QKV GEMM: Yz = Xz @ Wz^T =======================
// CTA 128x128, BK=32, cp.async double-buffered, 8 warps (2x4), warp 64x32. 2 CTAs/SM.
#define GST 36
#define G_SMEM (4*128*GST*4)   // 73728 B

__global__ __launch_bounds__(256,2)
void gemm_qkv(const float* __restrict__ x0, const float* __restrict__ x1,
              const float* __restrict__ x2,
              const float* __restrict__ w0, const float* __restrict__ w1,
              const float* __restrict__ w2,
              float* __restrict__ y0, float* __restrict__ y1,
              float* __restrict__ y2)
{
    extern __shared__ float sm[];
    float* As = sm;                 // [2][128][GST]
    float* Bs = sm + 2*128*GST;

    const int z = blockIdx.z;
    const float* X = z == 0 ? x0 : (z == 1 ? x1 : x2);
    const float* W = z == 0 ? w0 : (z == 1 ? w1 : w2);
    float*       Y = z == 0 ? y0 : (z == 1 ? y1 : y2);

    const int t = threadIdx.x, lane = t & 31, w = t >> 5;
    const int wm = w >> 2, wn = w & 3;
    const int r  = lane >> 2, cq = lane & 3;
    const int m0 = blockIdx.y << 7, n0 = blockIdx.x << 7;

    const uint32_t smbA = smem_u32(As), smbB = smem_u32(Bs);
    const int lrow = t >> 3, lc4 = (t & 7) << 2;

    float acc[4][4][4] = {};

    auto issue = [&](int kt, int buf){
        const uint32_t ab = smbA + buf * 128 * GST * 4;
        const uint32_t bb = smbB + buf * 128 * GST * 4;
#pragma unroll
        for (int i = 0; i < 4; i++){
            const int rr = lrow + i * 32;
            CPA16(ab + (rr * GST + lc4) * 4, X + (size_t)(m0 + rr) * DM + kt * 32 + lc4);
            CPA16(bb + (rr * GST + lc4) * 4, W + (size_t)(n0 + rr) * DM + kt * 32 + lc4);
        }
    };

    issue(0, 0); CPCOMMIT();
    issue(1, 1); CPCOMMIT();

    for (int kt = 0; kt < 24; kt++){
        const int b = kt & 1;
        if (kt < 23) CPWAIT(1); else CPWAIT(0);
        __syncthreads();

        const float* Ab = As + b * 128 * GST;
        const float* Bb = Bs + b * 128 * GST;
#pragma unroll
        for (int ks = 0; ks < 4; ks++){
            uint32_t af[4][4], bf[4][2];
#pragma unroll
            for (int mi = 0; mi < 4; mi++){
                const float* p = Ab + (wm * 64 + mi * 16 + r) * GST + ks * 8 + cq;
                af[mi][0] = f2tf(p[0]);
                af[mi][1] = f2tf(p[8 * GST]);
                af[mi][2] = f2tf(p[4]);
                af[mi][3] = f2tf(p[8 * GST + 4]);
            }
#pragma unroll
            for (int ni = 0; ni < 4; ni++){
                const float* p = Bb + (wn * 32 + ni * 8 + r) * GST + ks * 8 + cq;
                bf[ni][0] = f2tf(p[0]);
                bf[ni][1] = f2tf(p[4]);
            }
#pragma unroll
            for (int mi = 0; mi < 4; mi++)
#pragma unroll
                for (int ni = 0; ni < 4; ni++)
                    mma8(acc[mi][ni], af[mi], bf[ni]);
        }
        __syncthreads();
        if (kt + 2 < 24){ issue(kt + 2, b); CPCOMMIT(); }
    }

#pragma unroll
    for (int mi = 0; mi < 4; mi++)
#pragma unroll
    for (int ni = 0; ni < 4; ni++){
        const int col = n0 + wn * 32 + ni * 8 + cq * 2;
        const int h = col >> 6, d = col & 63;
#pragma unroll
        for (int rr = 0; rr < 2; rr++){
            const int grow = m0 + wm * 64 + mi * 16 + r + rr * 8;
            const int b_ = grow >> 11, s = grow & (SB - 1);
            float2 v = { tfb(acc[mi][ni][rr * 2 + 0]), tfb(acc[mi][ni][rr * 2 + 1]) };
            *(float2*)(Y + ((size_t)(b_ * NH + h) * SB + s) * DEP + d) = v;
        }
    }
}

// ======================= output GEMM: Y = ctx @ W^T + bias (ctx pre-rounded) ====
__global__ __launch_bounds__(256,2)
void gemm_out(const float* __restrict__ X, const float* __restrict__ W,
              float* __restrict__ Y, const float* __restrict__ bias)
{
    extern __shared__ float sm[];
    float* As = sm;
    float* Bs = sm + 2*128*GST;

    const int t = threadIdx.x, lane = t & 31, w = t >> 5;
    const int wm = w >> 2, wn = w & 3;
    const int r  = lane >> 2, cq = lane & 3;
    const int m0 = blockIdx.y << 7, n0 = blockIdx.x << 7;

    const uint32_t smbA = smem_u32(As), smbB = smem_u32(Bs);
    const int lrow = t >> 3, lc4 = (t & 7) << 2;

    float acc[4][4][4] = {};

    auto issue = [&](int kt, int buf){
        const uint32_t ab = smbA + buf * 128 * GST * 4;
        const uint32_t bb = smbB + buf * 128 * GST * 4;
#pragma unroll
        for (int i = 0; i < 4; i++){
            const int rr = lrow + i * 32;
            CPA16(ab + (rr * GST + lc4) * 4, X + (size_t)(m0 + rr) * DM + kt * 32 + lc4);
            CPA16(bb + (rr * GST + lc4) * 4, W + (size_t)(n0 + rr) * DM + kt * 32 + lc4);
        }
    };

    issue(0, 0); CPCOMMIT();
    issue(1, 1); CPCOMMIT();

    for (int kt = 0; kt < 24; kt++){
        const int b = kt & 1;
        if (kt < 23) CPWAIT(1); else CPWAIT(0);
        __syncthreads();

        const float* Ab = As + b * 128 * GST;
        const float* Bb = Bs + b * 128 * GST;
#pragma unroll
        for (int ks = 0; ks < 4; ks++){
            uint32_t af[4][4], bf[4][2];
#pragma unroll
            for (int mi = 0; mi < 4; mi++){
                const float* p = Ab + (wm * 64 + mi * 16 + r) * GST + ks * 8 + cq;
                af[mi][0] = __float_as_uint(p[0]);         // ctx pre-rounded
                af[mi][1] = __float_as_uint(p[8 * GST]);
                af[mi][2] = __float_as_uint(p[4]);
                af[mi][3] = __float_as_uint(p[8 * GST + 4]);
            }
#pragma unroll
            for (int ni = 0; ni < 4; ni++){
                const float* p = Bb + (wn * 32 + ni * 8 + r) * GST + ks * 8 + cq;
                bf[ni][0] = f2tf(p[0]);
                bf[ni][1] = f2tf(p[4]);
            }
#pragma unroll
            for (int mi = 0; mi < 4; mi++)
#pragma unroll
                for (int ni = 0; ni < 4; ni++)
                    mma8(acc[mi][ni], af[mi], bf[ni]);
        }
        __syncthreads();
        if (kt + 2 < 24){ issue(kt + 2, b); CPCOMMIT(); }
    }

#pragma unroll
    for (int mi = 0; mi < 4; mi++)
#pragma unroll
    for (int ni = 0; ni < 4; ni++){
        const int col = n0 + wn * 32 + ni * 8 + cq * 2;
        float2 bb = *(const float2*)(bias + col);
#pragma unroll
        for (int rr = 0; rr < 2; rr++){
            const int grow = m0 + wm * 64 + mi * 16 + r + rr * 8;
            float2 v = { acc[mi][ni][rr * 2 + 0] + bb.x, acc[mi][ni][rr * 2 + 1] + bb.y };
            *(float2*)(Y + (size_t)grow * DM + col) = v;
        }
    }
}

// ======================= flash attention (mma.sync tf32) =======================
// CTA: 128 q-rows, 4 warps (M=32/warp), key tiles of 64, cp.async 2-stage.
// Q/K/V pre-rounded tf32 bits. No max-subtraction; O accumulates in regs.
#define FST 68
#define F_TILE (64*FST)
#define F_SMEM ((4*F_TILE + 128*FST)*4)   // 104448 B -> 2 CTAs/SM

__global__ __launch_bounds__(128,2)
void flash_tc(const float* __restrict__ Qh, const float* __restrict__ Kh,
              const float* __restrict__ Vh, float* __restrict__ ctx,
              float* __restrict__ Lrow, float* __restrict__ attn)
{
    extern __shared__ float sm[];
    float* Ks = sm;                     // [2][64][FST]
    float* Vs = sm + 2 * F_TILE;        // [2][64][FST]
    float* Ps = sm + 4 * F_TILE;        // [128][FST]

    const int t = threadIdx.x, lane = t & 31, w = t >> 5;
    const int r = lane >> 2, cq = lane & 3;
    const int q0 = blockIdx.x << 7;
    const int bh = blockIdx.y;
    const int bi = bh / NH, h = bh % NH;
    const bool head0 = (h == 0);
    const float* Qb = Qh + (size_t)bh * SB * DEP;
    const float* Kb = Kh + (size_t)bh * SB * DEP;
    const float* Vb = Vh + (size_t)bh * SB * DEP;

    const uint32_t smbK = smem_u32(Ks), smbV = smem_u32(Vs);

    // Q fragments persistent (already tf32 bits)
    uint32_t aq[2][8][4];
#pragma unroll
    for (int mi = 0; mi < 2; mi++){
        const float* Q0 = Qb + (size_t)(q0 + w * 32 + mi * 16 + r) * DEP;
        const float* Q8 = Q0 + 8 * DEP;
#pragma unroll
        for (int ks = 0; ks < 8; ks++){
            aq[mi][ks][0] = __float_as_uint(Q0[ks * 8 + cq]);
            aq[mi][ks][1] = __float_as_uint(Q8[ks * 8 + cq]);
            aq[mi][ks][2] = __float_as_uint(Q0[ks * 8 + cq + 4]);
            aq[mi][ks][3] = __float_as_uint(Q8[ks * 8 + cq + 4]);
        }
    }

    auto issue = [&](int kt, int buf){
        const int k0 = kt << 6;
#pragma unroll
        for (int i = 0; i < 8; i++){
            int idx = t + i * 128;
            int row = idx >> 4, c4 = (idx & 15) << 2;
            CPA16(smbK + (buf * F_TILE + row * FST + c4) * 4,
                  Kb + (size_t)(k0 + row) * DEP + c4);
            CPA16(smbV + (buf * F_TILE + row * FST + c4) * 4,
                  Vb + (size_t)(k0 + row) * DEP + c4);
        }
    };

    issue(0, 0); CPCOMMIT();
    issue(1, 1); CPCOMMIT();

    float oacc[2][8][4] = {};
    float lr[4] = {0.f, 0.f, 0.f, 0.f};

    for (int kt = 0; kt < 32; kt++){
        const int b = kt & 1;
        if (kt < 31) CPWAIT(1); else CPWAIT(0);
        __syncthreads();

        // ---- S = Q K^T ----
        float sacc[2][8][4] = {};
        const float* Kt = Ks + b * F_TILE;
#pragma unroll
        for (int ks = 0; ks < 8; ks++){
#pragma unroll
            for (int ni = 0; ni < 8; ni++){
                uint32_t bf[2];
                const float* p = Kt + (ni * 8 + r) * FST + ks * 8 + cq;
                bf[0] = __float_as_uint(p[0]);
                bf[1] = __float_as_uint(p[4]);
                mma8(sacc[0][ni], aq[0][ks], bf);
                mma8(sacc[1][ni], aq[1][ks], bf);
            }
        }

        // ---- exp, row sums, P -> smem (+ head-0 attn, unnormalized) ----
#pragma unroll
        for (int mi = 0; mi < 2; mi++){
            float* Pr = Ps + (w * 32 + mi * 16 + r) * FST;
            float* ap0 = head0 ? attn + ((size_t)bi * SB + q0 + w * 32 + mi * 16 + r) * SB
                                 + (kt << 6)
                               : nullptr;
#pragma unroll
            for (int ni = 0; ni < 8; ni++){
                float e0 = __expf(sacc[mi][ni][0] * 0.125f);
                float e1 = __expf(sacc[mi][ni][1] * 0.125f);
                float e2 = __expf(sacc[mi][ni][2] * 0.125f);
                float e3 = __expf(sacc[mi][ni][3] * 0.125f);
                lr[mi * 2 + 0] += e0 + e1;
                lr[mi * 2 + 1] += e2 + e3;
                const int c = ni * 8 + cq * 2;
                *(float2*)(Pr + c)           = make_float2(tfb(e0), tfb(e1));
                *(float2*)(Pr + 8 * FST + c) = make_float2(tfb(e2), tfb(e3));
                if (head0){
                    *(float2*)(ap0 + c)                  = make_float2(e0, e1);
                    *(float2*)(ap0 + (size_t)8 * SB + c) = make_float2(e2, e3);
                }
            }
        }
        __syncwarp();

        // ---- O += P V ----
        const float* Vt = Vs + b * F_TILE;
#pragma unroll
        for (int ks = 0; ks < 8; ks++){
            uint32_t apf[2][4];
#pragma unroll
            for (int mi = 0; mi < 2; mi++){
                const float* pq = Ps + (w * 32 + mi * 16 + r) * FST + ks * 8 + cq;
                apf[mi][0] = __float_as_uint(pq[0]);
                apf[mi][1] = __float_as_uint(pq[8 * FST]);
                apf[mi][2] = __float_as_uint(pq[4]);
                apf[mi][3] = __float_as_uint(pq[8 * FST + 4]);
            }
#pragma unroll
            for (int ni = 0; ni < 8; ni++){
                uint32_t bf[2];
                const float* p = Vt + (ks * 8 + cq) * FST + ni * 8 + r;
                bf[0] = __float_as_uint(p[0]);
                bf[1] = __float_as_uint(p[4 * FST]);
                mma8(oacc[0][ni], apf[0], bf);
                mma8(oacc[1][ni], apf[1], bf);
            }
        }

        __syncthreads();
        if (kt + 2 < 32){ issue(kt + 2, b); CPCOMMIT(); }
    }

    // ---- epilogue (store ctx pre-rounded for the final GEMM) ----
#pragma unroll
    for (int i = 0; i < 4; i++){
        lr[i] += __shfl_xor_sync(0xffffffffu, lr[i], 1);
        lr[i] += __shfl_xor_sync(0xffffffffu, lr[i], 2);
    }
#pragma unroll
    for (int mi = 0; mi < 2; mi++){
        const int s0 = q0 + w * 32 + mi * 16 + r;
        const float inv0 = 1.f / lr[mi * 2], inv1 = 1.f / lr[mi * 2 + 1];
        float* c0p = ctx + ((size_t)bi * SB + s0) * DM + h * DEP;
        float* c1p = c0p + (size_t)8 * DM;
#pragma unroll
        for (int ni = 0; ni < 8; ni++){
            const int c = ni * 8 + cq * 2;
            *(float2*)(c0p + c) = make_float2(tfb(oacc[mi][ni][0] * inv0),
                                              tfb(oacc[mi][ni][1] * inv0));
            *(float2*)(c1p + c) = make_float2(tfb(oacc[mi][ni][2] * inv1),
                                              tfb(oacc[mi][ni][3] * inv1));
        }
        if (head0 && cq == 0){
            Lrow[(size_t)bi * SB + s0]     = lr[mi * 2];
            Lrow[(size_t)bi * SB + s0 + 8] = lr[mi * 2 + 1];
        }
    }
}

// ======================= attn head-0 normalize =======================
__global__ __launch_bounds__(256)
void attn_scale(float* __restrict__ attn, const float* __restrict__ Lrow)
{
    const int rowg = blockIdx.x;
    const float inv = 1.f / Lrow[rowg];
    float4* p = (float4*)(attn + (size_t)rowg * SB);
    for (int i = threadIdx.x; i < SB / 4; i += 256){
        float4 v = p[i];
        v.x *= inv; v.y *= inv; v.z *= inv; v.w *= inv;
        p[i] = v;
    }
}

// ======================= launch =======================
extern "C" void kernel_launch(void* const* d_in, const int* in_sizes, int n_in,
                              void* d_out, int out_size)
{
    const float* q  = (const float*)d_in[0];
    const float* k  = (const float*)d_in[1];
    const float* v  = (const float*)d_in[2];
    const float* wq = (const float*)d_in[3];
    const float* wk = (const float*)d_in[4];
    const float* wv = (const float*)d_in[5];
    const float* wd = (const float*)d_in[6];
    const float* bd = (const float*)d_in[7];
    float* out = (float*)d_out;

    float *Qh, *Kh, *Vh, *ctx, *Lr;
    cudaGetSymbolAddress((void**)&Qh,  g_Qh);
    cudaGetSymbolAddress((void**)&Kh,  g_Kh);
    cudaGetSymbolAddress((void**)&Vh,  g_Vh);
    cudaGetSymbolAddress((void**)&ctx, g_ctx);
    cudaGetSymbolAddress((void**)&Lr,  g_L);

    cudaFuncSetAttribute(gemm_qkv, cudaFuncAttributeMaxDynamicSharedMemorySize, G_SMEM);
    cudaFuncSetAttribute(gemm_out, cudaFuncAttributeMaxDynamicSharedMemorySize, G_SMEM);
    cudaFuncSetAttribute(flash_tc, cudaFuncAttributeMaxDynamicSharedMemorySize, F_SMEM);

    // one-time side stream + events (created on first (non-captured) call;
    // identical work is enqueued on every call)
    static cudaStream_t s1 = nullptr;
    static cudaEvent_t  evF = nullptr, evJ = nullptr;
    if (!s1){
        cudaStreamCreateWithFlags(&s1, cudaStreamNonBlocking);
        cudaEventCreateWithFlags(&evF, cudaEventDisableTiming);
        cudaEventCreateWithFlags(&evJ, cudaEventDisableTiming);
    }

    dim3 gq(DM / 128, (NB * SB) / 128, 3);    // 6 x 64 x 3 (Q,K,V fused)
    gemm_qkv<<<gq, 256, G_SMEM>>>(q, k, v, wq, wk, wv, Qh, Kh, Vh);

    const size_t OUTOFF = (size_t)NB * SB * DM;
    flash_tc<<<dim3(SB / 128, BHN), 128, F_SMEM>>>(Qh, Kh, Vh, ctx, Lr, out + OUTOFF);

    // fork: attn_scale on side stream, concurrent with gemm_out
    cudaEventRecord(evF, 0);
    cudaStreamWaitEvent(s1, evF, 0);
    attn_scale<<<NB * SB, 256, 0, s1>>>(out + OUTOFF, Lr);
    cudaEventRecord(evJ, s1);

    dim3 gg(DM / 128, (NB * SB) / 128);       // 6 x 64
    gemm_out<<<gg, 256, G_SMEM>>>(ctx, wd, out, bd);

    // join
    cudaStreamWaitEvent(0, evJ, 0);
}